// round 1
// baseline (speedup 1.0000x reference)
#include <cuda_runtime.h>

// ---------------------------------------------------------------------------
// DecoderLayer: B=4, S=1024, D=1024, H=16, hd=64, FFN=4096, fp32 throughout.
// Round 0: correctness baseline. All matmuls via tiled fp32 SGEMM (strided
// batched variant for attention), materialized scores + row softmax, fused
// add+LayerNorm. Scratch in __device__ globals (no allocations).
// ---------------------------------------------------------------------------

#define SEQ     1024
#define BATCH   4
#define DMODEL  1024
#define NHEADS  16
#define HDIM    64
#define FFNH    4096
#define ROWS    (BATCH * SEQ)          // 4096 token rows

// ------------------------- scratch (static device) -------------------------
__device__ float g_qkv [(long long)ROWS * 3 * DMODEL];     // 48 MB
__device__ float g_kv  [(long long)ROWS * 2 * DMODEL];     // 32 MB
__device__ float g_q   [(long long)ROWS * DMODEL];         // 16 MB
__device__ float g_sc  [(long long)BATCH * NHEADS * SEQ * SEQ]; // 256 MB
__device__ float g_attn[(long long)ROWS * DMODEL];         // 16 MB
__device__ float g_proj[(long long)ROWS * DMODEL];         // 16 MB
__device__ float g_y1  [(long long)ROWS * DMODEL];         // 16 MB
__device__ float g_y2  [(long long)ROWS * DMODEL];         // 16 MB
__device__ float g_ffn [(long long)ROWS * FFNH];           // 64 MB

// ---------------------------------------------------------------------------
// Generic strided-batched SGEMM.
//   C[M,N] = op( A[M,K] * B ) where B is [K,N] (row-major) or, if TRANSB,
//   B is [N,K] (row-major) and we multiply by B^T.
//   Batch index z = blockIdx.z decomposed as (b = z/H, h = z%H); each operand
//   gets base += b*s?b + h*s?h.
//   EPI: 0 = (+bias if non-null)            (projections)
//        1 = (+bias) then ReLU              (FFN1)
//        2 = *scale + mask[m*N+n]           (masked attention scores)
//        3 = *scale                         (unmasked attention scores)
// Requires: M%BM==0, N%BN==0, K%BK==0, all leading dims multiples of 4,
//           all base offsets multiples of 4 floats (verified for this layer).
// ---------------------------------------------------------------------------
template<int BM, int BN, int BK, int TM, int TN, bool TRANSB, int EPI>
__global__ __launch_bounds__(256)
void gemm_k(const float* __restrict__ A, const float* __restrict__ B,
            const float* __restrict__ bias, const float* __restrict__ mask,
            float* __restrict__ C,
            int M, int N, int K, int lda, int ldb, int ldc,
            long long sAb, long long sAh, long long sBb, long long sBh,
            long long sCb, long long sCh, int H, float scale)
{
    constexpr int THREADS = (BM / TM) * (BN / TN);
    static_assert(THREADS == 256, "tile config must give 256 threads");

    const int z  = blockIdx.z;
    const int bb = z / H;
    const int hh = z % H;
    A += (long long)bb * sAb + (long long)hh * sAh;
    B += (long long)bb * sBb + (long long)hh * sBh;
    C += (long long)bb * sCb + (long long)hh * sCh;

    __shared__ float As[BK][BM];
    __shared__ float Bs[BK][BN];

    const int tid = threadIdx.x;
    constexpr int NTX = BN / TN;
    const int tx = tid % NTX;
    const int ty = tid / NTX;
    const int m0 = blockIdx.y * BM;
    const int n0 = blockIdx.x * BN;

    float acc[TM][TN];
#pragma unroll
    for (int i = 0; i < TM; i++)
#pragma unroll
        for (int j = 0; j < TN; j++) acc[i][j] = 0.f;

    for (int k0 = 0; k0 < K; k0 += BK) {
        // ---- load A tile (BM x BK), stored transposed As[k][m] ----
        for (int i = tid; i < BM * BK / 4; i += THREADS) {
            const int ar = i / (BK / 4);
            const int ac = (i % (BK / 4)) * 4;
            const float4 v = *reinterpret_cast<const float4*>(
                &A[(long long)(m0 + ar) * lda + k0 + ac]);
            As[ac + 0][ar] = v.x; As[ac + 1][ar] = v.y;
            As[ac + 2][ar] = v.z; As[ac + 3][ar] = v.w;
        }
        // ---- load B tile into Bs[k][n] ----
        if (!TRANSB) {
            for (int i = tid; i < BK * BN / 4; i += THREADS) {
                const int br = i / (BN / 4);
                const int bc = (i % (BN / 4)) * 4;
                const float4 v = *reinterpret_cast<const float4*>(
                    &B[(long long)(k0 + br) * ldb + n0 + bc]);
                *reinterpret_cast<float4*>(&Bs[br][bc]) = v;
            }
        } else {
            // B is [N,K]; read along k (contiguous), scatter into Bs[k][n]
            for (int i = tid; i < BN * BK / 4; i += THREADS) {
                const int nr = i / (BK / 4);
                const int kc = (i % (BK / 4)) * 4;
                const float4 v = *reinterpret_cast<const float4*>(
                    &B[(long long)(n0 + nr) * ldb + k0 + kc]);
                Bs[kc + 0][nr] = v.x; Bs[kc + 1][nr] = v.y;
                Bs[kc + 2][nr] = v.z; Bs[kc + 3][nr] = v.w;
            }
        }
        __syncthreads();

#pragma unroll
        for (int kk = 0; kk < BK; kk++) {
            float ar[TM], br[TN];
#pragma unroll
            for (int i = 0; i < TM; i++) ar[i] = As[kk][ty * TM + i];
#pragma unroll
            for (int j = 0; j < TN; j++) br[j] = Bs[kk][tx * TN + j];
#pragma unroll
            for (int i = 0; i < TM; i++)
#pragma unroll
                for (int j = 0; j < TN; j++)
                    acc[i][j] += ar[i] * br[j];
        }
        __syncthreads();
    }

    // ---- epilogue ----
#pragma unroll
    for (int i = 0; i < TM; i++) {
        const int m = m0 + ty * TM + i;
#pragma unroll
        for (int j = 0; j < TN; j++) {
            const int n = n0 + tx * TN + j;
            float v = acc[i][j];
            if (EPI == 0 || EPI == 1) {
                if (bias) v += bias[n];
                if (EPI == 1) v = fmaxf(v, 0.f);
            } else {
                v *= scale;
                if (EPI == 2) v += mask[(long long)m * N + n];
            }
            C[(long long)m * ldc + n] = v;
        }
    }
}

// ---------------------------------------------------------------------------
// Row softmax over SEQ=1024 elements. One CTA (256 threads, 4 elems each).
// ---------------------------------------------------------------------------
__global__ __launch_bounds__(256)
void softmax_k(float* __restrict__ s)
{
    __shared__ float red[8];
    float* p = s + (long long)blockIdx.x * SEQ;
    const int tid = threadIdx.x;

    float v[4];
    float mx = -3.4e38f;
#pragma unroll
    for (int t = 0; t < 4; t++) { v[t] = p[tid + t * 256]; mx = fmaxf(mx, v[t]); }
#pragma unroll
    for (int o = 16; o > 0; o >>= 1) mx = fmaxf(mx, __shfl_xor_sync(0xffffffffu, mx, o));
    if ((tid & 31) == 0) red[tid >> 5] = mx;
    __syncthreads();
    float m2 = red[0];
#pragma unroll
    for (int w = 1; w < 8; w++) m2 = fmaxf(m2, red[w]);
    __syncthreads();

    float sum = 0.f;
#pragma unroll
    for (int t = 0; t < 4; t++) { v[t] = __expf(v[t] - m2); sum += v[t]; }
#pragma unroll
    for (int o = 16; o > 0; o >>= 1) sum += __shfl_xor_sync(0xffffffffu, sum, o);
    if ((tid & 31) == 0) red[tid >> 5] = sum;
    __syncthreads();
    float tot = 0.f;
#pragma unroll
    for (int w = 0; w < 8; w++) tot += red[w];

    const float inv = 1.f / tot;
#pragma unroll
    for (int t = 0; t < 4; t++) p[tid + t * 256] = v[t] * inv;
}

// ---------------------------------------------------------------------------
// out = LayerNorm(a + r) * gamma + beta, per row of DMODEL=1024.
// One CTA per row, 256 threads, 4 elems each (kept in registers).
// ---------------------------------------------------------------------------
__global__ __launch_bounds__(256)
void add_ln_k(const float* __restrict__ a, const float* __restrict__ r,
              const float* __restrict__ gam, const float* __restrict__ bet,
              float* __restrict__ out)
{
    __shared__ float red[8];
    const long long row = blockIdx.x;
    const float* pa = a + row * DMODEL;
    const float* pr = r + row * DMODEL;
    float* po = out + row * DMODEL;
    const int tid = threadIdx.x;

    float v[4];
    float s = 0.f;
#pragma unroll
    for (int t = 0; t < 4; t++) {
        const int c = tid + t * 256;
        v[t] = pa[c] + pr[c];
        s += v[t];
    }
#pragma unroll
    for (int o = 16; o > 0; o >>= 1) s += __shfl_xor_sync(0xffffffffu, s, o);
    if ((tid & 31) == 0) red[tid >> 5] = s;
    __syncthreads();
    float tot = 0.f;
#pragma unroll
    for (int w = 0; w < 8; w++) tot += red[w];
    __syncthreads();
    const float mean = tot * (1.f / DMODEL);

    float q = 0.f;
#pragma unroll
    for (int t = 0; t < 4; t++) { const float d = v[t] - mean; q += d * d; }
#pragma unroll
    for (int o = 16; o > 0; o >>= 1) q += __shfl_xor_sync(0xffffffffu, q, o);
    if ((tid & 31) == 0) red[tid >> 5] = q;
    __syncthreads();
    float qt = 0.f;
#pragma unroll
    for (int w = 0; w < 8; w++) qt += red[w];

    const float inv = rsqrtf(qt * (1.f / DMODEL) + 1e-5f);
#pragma unroll
    for (int t = 0; t < 4; t++) {
        const int c = tid + t * 256;
        po[c] = gam[c] * (v[t] - mean) * inv + bet[c];
    }
}

// ---------------------------------------------------------------------------
extern "C" void kernel_launch(void* const* d_in, const int* in_sizes, int n_in,
                              void* d_out, int out_size)
{
    const float* x      = (const float*)d_in[0];
    const float* y      = (const float*)d_in[1];
    const float* mask   = (const float*)d_in[2];
    const float* w_qkv  = (const float*)d_in[3];
    const float* b_qkv  = (const float*)d_in[4];
    const float* w_so   = (const float*)d_in[5];
    const float* b_so   = (const float*)d_in[6];
    const float* gamma1 = (const float*)d_in[7];
    const float* beta1  = (const float*)d_in[8];
    const float* w_kv   = (const float*)d_in[9];
    const float* b_kv   = (const float*)d_in[10];
    const float* w_q    = (const float*)d_in[11];
    const float* b_q    = (const float*)d_in[12];
    const float* w_co   = (const float*)d_in[13];
    const float* b_co   = (const float*)d_in[14];
    const float* gamma2 = (const float*)d_in[15];
    const float* beta2  = (const float*)d_in[16];
    const float* w_f1   = (const float*)d_in[17];
    const float* b_f1   = (const float*)d_in[18];
    const float* w_f2   = (const float*)d_in[19];
    const float* b_f2   = (const float*)d_in[20];
    const float* gamma3 = (const float*)d_in[21];
    const float* beta3  = (const float*)d_in[22];
    float* out = (float*)d_out;

    float *qkv, *kv, *q, *sc, *attn, *proj, *y1, *y2, *ffn;
    cudaGetSymbolAddress((void**)&qkv,  g_qkv);
    cudaGetSymbolAddress((void**)&kv,   g_kv);
    cudaGetSymbolAddress((void**)&q,    g_q);
    cudaGetSymbolAddress((void**)&sc,   g_sc);
    cudaGetSymbolAddress((void**)&attn, g_attn);
    cudaGetSymbolAddress((void**)&proj, g_proj);
    cudaGetSymbolAddress((void**)&y1,   g_y1);
    cudaGetSymbolAddress((void**)&y2,   g_y2);
    cudaGetSymbolAddress((void**)&ffn,  g_ffn);

    const float SCALE = 0.125f;              // 1/sqrt(64)
    const dim3 T(256);
    const long long SD3 = (long long)SEQ * 3 * DMODEL;   // qkv batch stride
    const long long SD2 = (long long)SEQ * 2 * DMODEL;   // kv batch stride
    const long long SD  = (long long)SEQ * DMODEL;
    const long long SS  = (long long)SEQ * SEQ;

    // ---- self attention on y ----
    // 1. qkv = y @ w_qkv + b_qkv   [4096 x 3072]
    gemm_k<128,128,8,8,8,false,0><<<dim3(24,32,1), T>>>(
        y, w_qkv, b_qkv, nullptr, qkv, ROWS, 3*DMODEL, DMODEL,
        DMODEL, 3*DMODEL, 3*DMODEL, 0,0,0,0,0,0, 1, 0.f);
    // 2. scores = q @ k^T * scale + mask   per (b,h): [1024x1024], K=64
    gemm_k<128,128,8,8,8,true,2><<<dim3(8,8,BATCH*NHEADS), T>>>(
        qkv, qkv + HDIM, nullptr, mask, sc, SEQ, SEQ, HDIM,
        3*DMODEL, 3*DMODEL, SEQ,
        SD3, 3*HDIM, SD3, 3*HDIM, (long long)NHEADS*SS, SS, NHEADS, SCALE);
    // 3. softmax rows
    softmax_k<<<BATCH*NHEADS*SEQ, 256>>>(sc);
    // 4. vals = P @ V  -> stored [b][h][s][d] contiguous (= buggy reshape layout)
    gemm_k<128,64,8,8,4,false,0><<<dim3(1,8,BATCH*NHEADS), T>>>(
        sc, qkv + 2*HDIM, nullptr, nullptr, attn, SEQ, HDIM, SEQ,
        SEQ, 3*DMODEL, HDIM,
        (long long)NHEADS*SS, SS, SD3, 3*HDIM,
        (long long)NHEADS*SEQ*HDIM, (long long)SEQ*HDIM, NHEADS, 0.f);
    // 5. proj = vals @ w_so + b_so
    gemm_k<128,128,8,8,8,false,0><<<dim3(8,32,1), T>>>(
        attn, w_so, b_so, nullptr, proj, ROWS, DMODEL, DMODEL,
        DMODEL, DMODEL, DMODEL, 0,0,0,0,0,0, 1, 0.f);
    // 6. y1 = LN(proj + y)
    add_ln_k<<<ROWS, 256>>>(proj, y, gamma1, beta1, y1);

    // ---- cross attention: kv from x, q from y1 ----
    // 7. kv = x @ w_kv + b_kv   [4096 x 2048]
    gemm_k<128,128,8,8,8,false,0><<<dim3(16,32,1), T>>>(
        x, w_kv, b_kv, nullptr, kv, ROWS, 2*DMODEL, DMODEL,
        DMODEL, 2*DMODEL, 2*DMODEL, 0,0,0,0,0,0, 1, 0.f);
    // 8. q = y1 @ w_q + b_q
    gemm_k<128,128,8,8,8,false,0><<<dim3(8,32,1), T>>>(
        y1, w_q, b_q, nullptr, q, ROWS, DMODEL, DMODEL,
        DMODEL, DMODEL, DMODEL, 0,0,0,0,0,0, 1, 0.f);
    // 9. scores = q @ k^T * scale (no mask)
    gemm_k<128,128,8,8,8,true,3><<<dim3(8,8,BATCH*NHEADS), T>>>(
        q, kv, nullptr, nullptr, sc, SEQ, SEQ, HDIM,
        DMODEL, 2*DMODEL, SEQ,
        SD, HDIM, SD2, 2*HDIM, (long long)NHEADS*SS, SS, NHEADS, SCALE);
    // 10. softmax
    softmax_k<<<BATCH*NHEADS*SEQ, 256>>>(sc);
    // 11. vals = P @ V  -> properly transposed to [B,S,H*hd]
    gemm_k<128,64,8,8,4,false,0><<<dim3(1,8,BATCH*NHEADS), T>>>(
        sc, kv + HDIM, nullptr, nullptr, attn, SEQ, HDIM, SEQ,
        SEQ, 2*DMODEL, DMODEL,
        (long long)NHEADS*SS, SS, SD2, 2*HDIM,
        SD, HDIM, NHEADS, 0.f);
    // 12. proj = vals @ w_co + b_co
    gemm_k<128,128,8,8,8,false,0><<<dim3(8,32,1), T>>>(
        attn, w_co, b_co, nullptr, proj, ROWS, DMODEL, DMODEL,
        DMODEL, DMODEL, DMODEL, 0,0,0,0,0,0, 1, 0.f);
    // 13. y2 = LN(proj + y1)
    add_ln_k<<<ROWS, 256>>>(proj, y1, gamma2, beta2, y2);

    // ---- FFN ----
    // 14. ffn = relu(y2 @ w_f1 + b_f1)   [4096 x 4096]
    gemm_k<128,128,8,8,8,false,1><<<dim3(32,32,1), T>>>(
        y2, w_f1, b_f1, nullptr, ffn, ROWS, FFNH, DMODEL,
        DMODEL, FFNH, FFNH, 0,0,0,0,0,0, 1, 0.f);
    // 15. proj = ffn @ w_f2 + b_f2
    gemm_k<128,128,8,8,8,false,0><<<dim3(8,32,1), T>>>(
        ffn, w_f2, b_f2, nullptr, proj, ROWS, DMODEL, FFNH,
        FFNH, DMODEL, DMODEL, 0,0,0,0,0,0, 1, 0.f);
    // 16. out = LN(proj + y2)
    add_ln_k<<<ROWS, 256>>>(proj, y2, gamma3, beta3, out);
}